// round 9
// baseline (speedup 1.0000x reference)
#include <cuda_runtime.h>
#include <math.h>
#include <stdint.h>

// Problem constants
#define H   516
#define T   512
#define B   64
#define NY  20
#define SEQ 20
#define G4  2064      /* 4*H */
#define H2  1032      /* 2*H */
#define TB  32768     /* T*B */

// ------------------------- scratch (device globals) -------------------------
__device__ float g_xe[TB * 256];
__device__ float g_Gx[2 * TB * G4];
__device__ float g_out0[TB * H2];
__device__ float g_outenc[TB * H2];
__device__ float g_E2[TB * H2];
__device__ float g_eh[2 * 2 * B * H];       // [parity][dir][B][H]
__device__ float g_ec[2 * 2 * B * H];
__device__ float g_dh[2 * 4 * B * H];       // [parity][slot4][B][H]
__device__ float g_dc[2 * 4 * B * H];
__device__ float g_l0[B * H2];
__device__ float g_cc[B * 2 * H2];          // [outdec | context]
__device__ float g_dbuf[B * H2];
__device__ float g_co[B * H2];
__device__ float g_score[B * T];
__device__ float g_loss[1];
__device__ unsigned g_bcount = 0;
__device__ unsigned g_bgen = 0;

// --------------------------- f32x2 packed helpers ---------------------------
__device__ __forceinline__ void fma2(unsigned long long& d,
                                     unsigned long long a,
                                     unsigned long long b) {
    asm("fma.rn.f32x2 %0, %1, %2, %0;" : "+l"(d) : "l"(a), "l"(b));
}
__device__ __forceinline__ unsigned long long pack2(float lo, float hi) {
    unsigned long long r;
    asm("mov.b64 %0, {%1, %2};" : "=l"(r) : "f"(lo), "f"(hi));
    return r;
}
__device__ __forceinline__ void unpack2(unsigned long long v, float& lo, float& hi) {
    asm("mov.b64 {%0, %1}, %2;" : "=f"(lo), "=f"(hi) : "l"(v));
}

// -------------------------- software grid barrier ---------------------------
__device__ __forceinline__ void grid_barrier(unsigned nb) {
    __syncthreads();
    if (threadIdx.x == 0) {
        __threadfence();
        unsigned gen = *(volatile unsigned*)&g_bgen;
        if (atomicAdd(&g_bcount, 1) == nb - 1) {
            atomicExch(&g_bcount, 0);
            __threadfence();
            atomicAdd(&g_bgen, 1);
        } else {
            while (*(volatile unsigned*)&g_bgen == gen) {}
        }
        __threadfence();
    }
    __syncthreads();
}

// ------------------------------ small kernels -------------------------------
__global__ void zero_kernel(float* p, int n) {
    int i = blockIdx.x * 256 + threadIdx.x;
    if (i < n) p[i] = 0.f;
}

__global__ void write_out_kernel(float* out, const float* loss) {
    out[0] = loss[0];
}

__global__ void copy2_kernel(const float* sh, const float* sc,
                             float* dh, float* dc, int n) {
    int i = blockIdx.x * 256 + threadIdx.x;
    if (i < n) { dh[i] = sh[i]; dc[i] = sc[i]; }
}

__global__ void expand_kernel(const float* __restrict__ x,
                              const float* __restrict__ We,
                              const float* __restrict__ be,
                              float* __restrict__ xe) {
    int row = blockIdx.x;
    int c = threadIdx.x;
    const float* xr = x + row * 4;
    const float* w = We + c * 4;
    xe[(size_t)row * 256 + c] =
        be[c] + xr[0] * w[0] + xr[1] * w[1] + xr[2] * w[2] + xr[3] * w[3];
}

// ----------------------- big SGEMM: C = A @ B^T + bias ----------------------
// f32x2 packed-FMA inner product. M%128==0, K%8==0; N-edge guarded.
__global__ void sgemm_nt_kernel(int M, int N, int K,
                                const float* __restrict__ A, int lda,
                                const float* __restrict__ Bm, int ldb,
                                const float* __restrict__ bias,
                                float* __restrict__ C, int ldc) {
    __shared__ float As[8][128];
    __shared__ float Bs[8][128];
    const int tid = threadIdx.x;
    const int row0 = blockIdx.y * 128, col0 = blockIdx.x * 128;
    const int lrow = tid >> 1;
    const int lcol = (tid & 1) * 4;
    const int tx = tid & 15, ty = tid >> 4;

    unsigned long long accp[8][4];
#pragma unroll
    for (int i = 0; i < 8; i++)
#pragma unroll
        for (int j = 0; j < 4; j++) accp[i][j] = 0ull;

    const float* Ag = A + (size_t)(row0 + lrow) * lda + lcol;
    const float* Bg = Bm + (size_t)(col0 + lrow) * ldb + lcol;
    const bool bvalid = (col0 + lrow) < N;

    for (int k0 = 0; k0 < K; k0 += 8) {
        float4 av = *(const float4*)(Ag + k0);
        float4 bv = make_float4(0.f, 0.f, 0.f, 0.f);
        if (bvalid) bv = *(const float4*)(Bg + k0);
        __syncthreads();
        As[lcol + 0][lrow] = av.x; As[lcol + 1][lrow] = av.y;
        As[lcol + 2][lrow] = av.z; As[lcol + 3][lrow] = av.w;
        Bs[lcol + 0][lrow] = bv.x; Bs[lcol + 1][lrow] = bv.y;
        Bs[lcol + 2][lrow] = bv.z; Bs[lcol + 3][lrow] = bv.w;
        __syncthreads();
#pragma unroll
        for (int k = 0; k < 8; k++) {
            float a0[8];
            *(float4*)&a0[0] = *(const float4*)&As[k][ty * 8];
            *(float4*)&a0[4] = *(const float4*)&As[k][ty * 8 + 4];
            const unsigned long long* Bp =
                (const unsigned long long*)&Bs[k][tx * 8];
            unsigned long long bp0 = Bp[0], bp1 = Bp[1],
                               bp2 = Bp[2], bp3 = Bp[3];
#pragma unroll
            for (int i = 0; i < 8; i++) {
                unsigned long long ap = pack2(a0[i], a0[i]);
                fma2(accp[i][0], ap, bp0);
                fma2(accp[i][1], ap, bp1);
                fma2(accp[i][2], ap, bp2);
                fma2(accp[i][3], ap, bp3);
            }
        }
    }
#pragma unroll
    for (int i = 0; i < 8; i++) {
        int r = row0 + ty * 8 + i;
#pragma unroll
        for (int jj = 0; jj < 4; jj++) {
            float v0, v1;
            unpack2(accp[i][jj], v0, v1);
            int c0 = col0 + tx * 8 + 2 * jj;
            if (c0 < N) {
                if (bias) v0 += bias[c0];
                C[(size_t)r * ldc + c0] = v0;
            }
            if (c0 + 1 < N) {
                if (bias) v1 += bias[c0 + 1];
                C[(size_t)r * ldc + c0 + 1] = v1;
            }
        }
    }
}

// ------------- persistent encoder layer: all T steps in one launch ----------
// grid (129, 2 dirs), 256 threads, co-resident (launch_bounds 256,2).
__global__ void __launch_bounds__(256, 2)
enc_persist_kernel(const float* __restrict__ Gx,   // [2][TB*G4]
                   const float* __restrict__ Wh,   // [2][G4][H]
                   float* __restrict__ h,          // [2 parity][2 dir][B][H]
                   float* __restrict__ c,
                   float* __restrict__ outseq) {   // [T][B][H2]
    const int dir = blockIdx.y;
    const int j0 = blockIdx.x * 4;
    const int tid = threadIdx.x;
    const int tx = tid & 15, ty = tid >> 4, rb = ty * 4;
    const unsigned nb = gridDim.x * gridDim.y;

    __shared__ float Wsf[16][517];     // padded: conflict-free tx-row reads
    __shared__ float As[2][12][68];
    __shared__ float gsm[64][17];

    // hoist Wh tile once (stays for all 512 steps)
    const float* whd = Wh + (size_t)dir * G4 * H;
    for (int idx = tid; idx < 16 * H; idx += 256) {
        int r = idx / H, k = idx % H;
        int rq = r >> 2, ru = r & 3;
        Wsf[r][k] = whd[(size_t)(rq * H + j0 + ru) * H + k];
    }
    __syncthreads();

    const int SBH_ = B * H, S2_ = 2 * SBH_;
    const int eb0 = tid / 12,         ek0 = tid % 12;
    const int eb1 = (tid + 256) / 12, ek1 = (tid + 256) % 12;
    const int eb2 = (tid + 512) / 12, ek2 = (tid + 512) % 12;

    for (int s = 0; s < T; s++) {
        const int t = dir ? (T - 1 - s) : s;
        const float* hp = h + (s & 1) * S2_ + dir * SBH_;
        float* hn = h + ((s + 1) & 1) * S2_ + dir * SBH_;
        const float* cp_ = c + (s & 1) * S2_ + dir * SBH_;
        float* cn_ = c + ((s + 1) & 1) * S2_ + dir * SBH_;

        // stage chunk 0
        As[0][ek0][eb0] = hp[eb0 * H + ek0];
        As[0][ek1][eb1] = hp[eb1 * H + ek1];
        As[0][ek2][eb2] = hp[eb2 * H + ek2];
        __syncthreads();

        unsigned long long acc01 = 0ull, acc23 = 0ull;
        for (int kc = 0; kc < 43; kc++) {     // 516 = 43*12
            const int buf = kc & 1;
            float pf0 = 0.f, pf1 = 0.f, pf2 = 0.f;
            if (kc < 42) {
                int base = (kc + 1) * 12;
                pf0 = hp[eb0 * H + base + ek0];
                pf1 = hp[eb1 * H + base + ek1];
                pf2 = hp[eb2 * H + base + ek2];
            }
#pragma unroll
            for (int kk = 0; kk < 12; kk++) {
                const unsigned long long* h2 =
                    (const unsigned long long*)&As[buf][kk][rb];
                unsigned long long h01 = h2[0], h23 = h2[1];
                float w = Wsf[tx][kc * 12 + kk];
                unsigned long long wp = pack2(w, w);
                fma2(acc01, wp, h01);
                fma2(acc23, wp, h23);
            }
            if (kc < 42) {
                As[buf ^ 1][ek0][eb0] = pf0;
                As[buf ^ 1][ek1][eb1] = pf1;
                As[buf ^ 1][ek2][eb2] = pf2;
            }
            __syncthreads();
        }

        float a0, a1, a2, a3;
        unpack2(acc01, a0, a1);
        unpack2(acc23, a2, a3);
        gsm[rb + 0][tx] = a0; gsm[rb + 1][tx] = a1;
        gsm[rb + 2][tx] = a2; gsm[rb + 3][tx] = a3;
        __syncthreads();

        {
            int bb = tid >> 2, uu = tid & 3;
            int j = j0 + uu;
            const float* gx = Gx + (size_t)dir * TB * G4
                              + ((size_t)t * B + bb) * G4 + j;
            float gi = gsm[bb][uu]      + gx[0];
            float gf = gsm[bb][4 + uu]  + gx[H];
            float gg = gsm[bb][8 + uu]  + gx[2 * H];
            float go = gsm[bb][12 + uu] + gx[3 * H];
            float cp = cp_[bb * H + j];
            float si = 1.f / (1.f + expf(-gi));
            float sf = 1.f / (1.f + expf(-gf));
            float so = 1.f / (1.f + expf(-go));
            float cn = fmaf(sf, cp, si * tanhf(gg));
            float hn_ = so * tanhf(cn);
            cn_[bb * H + j] = cn;
            hn[bb * H + j] = hn_;
            outseq[((size_t)t * B + bb) * H2 + dir * H + j] = hn_;
        }
        if (s < T - 1) grid_barrier(nb);
    }
}

// ------------------------- decoder LSTM cell (1 step) -----------------------
__global__ void dec_cell_kernel(const float* __restrict__ x, int Kx,
                                const float* __restrict__ Wi,
                                const float* __restrict__ Wh,
                                const float* __restrict__ bias,
                                const float* __restrict__ hprev, float* __restrict__ hnext,
                                const float* __restrict__ cprev, float* __restrict__ cnext,
                                float* __restrict__ outcat, int outld) {
    const int dir = blockIdx.y;
    const int j0 = blockIdx.x * 4;
    const int tid = threadIdx.x;
    const int tx = tid & 15, ty = tid >> 4, rb = ty * 4;

    __shared__ float As[12][68];
    __shared__ float Ws[16][13];
    __shared__ float gsm[64][17];

    float acc0 = 0.f, acc1 = 0.f, acc2 = 0.f, acc3 = 0.f;

    for (int ph = 0; ph < 2; ph++) {
        const float* A = (ph == 0) ? x : (hprev + dir * (B * H));
        const int K = (ph == 0) ? Kx : H;
        const float* W = (ph == 0) ? (Wi + (size_t)dir * G4 * Kx)
                                   : (Wh + (size_t)dir * G4 * H);
        for (int k0 = 0; k0 < K; k0 += 12) {
            int rem = K - k0; if (rem > 12) rem = 12;
            for (int idx = tid; idx < 64 * 12; idx += 256) {
                int bb = idx / 12, kk = idx % 12;
                As[kk][bb] = (kk < rem) ? A[bb * K + k0 + kk] : 0.f;
            }
            if (tid < 192) {
                int r = tid / 12, kk = tid % 12;
                int rq = r >> 2, ru = r & 3;
                float wv = 0.f;
                if (kk < rem)
                    wv = W[(size_t)(rq * H + j0 + ru) * K + k0 + kk];
                Ws[r][kk] = wv;
            }
            __syncthreads();
#pragma unroll
            for (int kk = 0; kk < 12; kk++) {
                float4 hv = *(const float4*)&As[kk][rb];
                float w = Ws[tx][kk];
                acc0 = fmaf(hv.x, w, acc0);
                acc1 = fmaf(hv.y, w, acc1);
                acc2 = fmaf(hv.z, w, acc2);
                acc3 = fmaf(hv.w, w, acc3);
            }
            __syncthreads();
        }
    }

    gsm[rb + 0][tx] = acc0; gsm[rb + 1][tx] = acc1;
    gsm[rb + 2][tx] = acc2; gsm[rb + 3][tx] = acc3;
    __syncthreads();

    {
        int bb = tid >> 2, uu = tid & 3;
        int j = j0 + uu;
        const float* bz = bias + dir * G4;
        float gi = gsm[bb][uu]      + bz[j];
        float gf = gsm[bb][4 + uu]  + bz[H + j];
        float gg = gsm[bb][8 + uu]  + bz[2 * H + j];
        float go = gsm[bb][12 + uu] + bz[3 * H + j];
        float cp = cprev[dir * B * H + bb * H + j];
        float si = 1.f / (1.f + expf(-gi));
        float sf = 1.f / (1.f + expf(-gf));
        float so = 1.f / (1.f + expf(-go));
        float cn = fmaf(sf, cp, si * tanhf(gg));
        float hn = so * tanhf(cn);
        cnext[dir * B * H + bb * H + j] = cn;
        hnext[dir * B * H + bb * H + j] = hn;
        outcat[bb * outld + dir * H + j] = hn;
    }
}

// -------------------- skinny GEMM: C[64,N] = A@W^T (+b, tanh) ---------------
__global__ void skinny64_nt_kernel(int N, int K,
                                   const float* __restrict__ A, int lda,
                                   const float* __restrict__ W, int ldw,
                                   const float* __restrict__ bias,
                                   float* __restrict__ C, int ldc, int act) {
    __shared__ float As[16][68];
    __shared__ float Ws[16][17];
    const int tid = threadIdx.x;
    const int tx = tid & 15, ty = tid >> 4;
    const int col = blockIdx.x * 16 + tx;

    float acc[4] = {0.f, 0.f, 0.f, 0.f};

    for (int k0 = 0; k0 < K; k0 += 16) {
        for (int idx = tid; idx < 64 * 16; idx += 256) {
            int r = idx >> 4, kk = idx & 15;
            As[kk][r] = (k0 + kk < K) ? A[(size_t)r * lda + k0 + kk] : 0.f;
        }
        {
            int cix = tid & 15, kk = tid >> 4;
            int cg = blockIdx.x * 16 + cix;
            float wv = 0.f;
            if (cg < N && (k0 + kk) < K)
                wv = W[(size_t)cg * ldw + k0 + kk];
            Ws[cix][kk] = wv;
        }
        __syncthreads();
#pragma unroll
        for (int kk = 0; kk < 16; kk++) {
            float w = Ws[tx][kk];
            float4 a = *(const float4*)&As[kk][ty * 4];
            acc[0] = fmaf(a.x, w, acc[0]);
            acc[1] = fmaf(a.y, w, acc[1]);
            acc[2] = fmaf(a.z, w, acc[2]);
            acc[3] = fmaf(a.w, w, acc[3]);
        }
        __syncthreads();
    }

    if (col < N) {
#pragma unroll
        for (int i = 0; i < 4; i++) {
            int r = ty * 4 + i;
            float v = acc[i];
            if (bias) v += bias[col];
            if (act) v = tanhf(v);
            C[(size_t)r * ldc + col] = v;
        }
    }
}

// ------------------------------ attention ----------------------------------
__global__ void score_kernel(const float* __restrict__ E2,
                             const float* __restrict__ dbuf,
                             const float* __restrict__ v,
                             float* __restrict__ score) {
    int w = blockIdx.x * 8 + (threadIdx.x >> 5);
    int lane = threadIdx.x & 31;
    int bb = w & 63, t = w >> 6;
    const float* e = E2 + (size_t)w * H2;
    const float* d = dbuf + bb * H2;
    float s = 0.f;
    for (int hh = lane; hh < H2; hh += 32)
        s += v[hh] * tanhf(e[hh] + d[hh]);
#pragma unroll
    for (int o = 16; o > 0; o >>= 1)
        s += __shfl_down_sync(0xffffffffu, s, o);
    if (lane == 0) score[bb * T + t] = s;
}

// fused softmax over T + context accumulation. block = b, 512 threads.
__global__ void attn_kernel(const float* __restrict__ score,
                            const float* __restrict__ enc,
                            float* __restrict__ cc) {
    __shared__ float sm[T];
    __shared__ float aws[T];
    int bb = blockIdx.x, tid = threadIdx.x;
    float v = score[bb * T + tid];
    sm[tid] = v;
    __syncthreads();
    for (int st = 256; st > 0; st >>= 1) {
        if (tid < st) sm[tid] = fmaxf(sm[tid], sm[tid + st]);
        __syncthreads();
    }
    float mx = sm[0];
    __syncthreads();
    float e = expf(v - mx);
    sm[tid] = e;
    __syncthreads();
    for (int st = 256; st > 0; st >>= 1) {
        if (tid < st) sm[tid] += sm[tid + st];
        __syncthreads();
    }
    aws[tid] = e / sm[0];
    __syncthreads();

    float acc[3] = {0.f, 0.f, 0.f};
    for (int t = 0; t < T; t++) {
        float wt = aws[t];
        const float* ep = enc + ((size_t)t * B + bb) * H2;
#pragma unroll
        for (int j = 0; j < 3; j++) {
            int hh = tid + j * 512;
            if (hh < H2) acc[j] = fmaf(wt, ep[hh], acc[j]);
        }
    }
#pragma unroll
    for (int j = 0; j < 3; j++) {
        int hh = tid + j * 512;
        if (hh < H2) cc[bb * (2 * H2) + H2 + hh] = acc[j];
    }
}

// -------------- fused logits + cross-entropy (single block, det.) -----------
__global__ void ce_fused_kernel(const float* __restrict__ co,
                                const float* __restrict__ out_W,
                                const float* __restrict__ out_b,
                                const int* __restrict__ lab,
                                float* __restrict__ loss) {
    __shared__ float lg[64][20];
    __shared__ float red[64];
    int tid = threadIdx.x;           // 1024 threads
    int bb = tid >> 4, slot = tid & 15;
    for (int cix = slot; cix < SEQ; cix += 16) {
        const float* a = co + bb * H2;
        const float* w = out_W + cix * H2;
        float s = out_b[cix];
#pragma unroll 4
        for (int k = 0; k < H2; k++) s = fmaf(a[k], w[k], s);
        lg[bb][cix] = s;
    }
    __syncthreads();
    if (slot == 0) {
        float m = lg[bb][0];
#pragma unroll
        for (int i = 1; i < SEQ; i++) m = fmaxf(m, lg[bb][i]);
        float s = 0.f;
#pragma unroll
        for (int i = 0; i < SEQ; i++) s += expf(lg[bb][i] - m);
        red[bb] = -(lg[bb][lab[bb]] - m - logf(s));
    }
    __syncthreads();
    if (tid == 0) {
        float tot = 0.f;
        for (int i = 0; i < 64; i++) tot += red[i];
        loss[0] += tot / 64.f;
    }
}

// ------------------------------- host --------------------------------------
static float* symaddr(const void* devsym) {
    void* p = nullptr;
    cudaGetSymbolAddress(&p, devsym);
    return (float*)p;
}

extern "C" void kernel_launch(void* const* d_in, const int* in_sizes, int n_in,
                              void* d_out, int out_size) {
    (void)in_sizes; (void)n_in; (void)out_size;
    const float* x        = (const float*)d_in[0];
    const float* y        = (const float*)d_in[1];
    const int*   label    = (const int*)d_in[2];
    const float* expand_W = (const float*)d_in[3];
    const float* expand_b = (const float*)d_in[4];
    const float* eWi0     = (const float*)d_in[5];
    const float* eWh0     = (const float*)d_in[6];
    const float* eb0      = (const float*)d_in[7];
    const float* eWi1     = (const float*)d_in[8];
    const float* eWh1     = (const float*)d_in[9];
    const float* eb1      = (const float*)d_in[10];
    const float* dWi0     = (const float*)d_in[11];
    const float* dWh0     = (const float*)d_in[12];
    const float* db0      = (const float*)d_in[13];
    const float* dWi1     = (const float*)d_in[14];
    const float* dWh1     = (const float*)d_in[15];
    const float* db1      = (const float*)d_in[16];
    const float* attn_W   = (const float*)d_in[17];
    const float* attn_b   = (const float*)d_in[18];
    const float* attn_v   = (const float*)d_in[19];
    const float* concat_W = (const float*)d_in[20];
    const float* concat_b = (const float*)d_in[21];
    const float* out_W    = (const float*)d_in[22];
    const float* out_b    = (const float*)d_in[23];

    float* xe     = symaddr(&g_xe);
    float* Gx     = symaddr(&g_Gx);
    float* out0   = symaddr(&g_out0);
    float* outenc = symaddr(&g_outenc);
    float* E2     = symaddr(&g_E2);
    float* eh     = symaddr(&g_eh);
    float* ec     = symaddr(&g_ec);
    float* dh     = symaddr(&g_dh);
    float* dc     = symaddr(&g_dc);
    float* l0     = symaddr(&g_l0);
    float* cc     = symaddr(&g_cc);
    float* dbuf   = symaddr(&g_dbuf);
    float* co     = symaddr(&g_co);
    float* score  = symaddr(&g_score);
    float* loss   = symaddr(&g_loss);

    const int SBH = B * H;
    const int S2  = 2 * SBH;
    const int S4  = 4 * SBH;

    zero_kernel<<<1, 32>>>(loss, 1);
    zero_kernel<<<(S2 + 255) / 256, 256>>>(eh, S2);
    zero_kernel<<<(S2 + 255) / 256, 256>>>(ec, S2);

    expand_kernel<<<TB, 256>>>(x, expand_W, expand_b, xe);

    // ---- encoder layer 0 ----
    for (int dir = 0; dir < 2; dir++) {
        sgemm_nt_kernel<<<dim3((G4 + 127) / 128, TB / 128), 256>>>(
            TB, G4, 256, xe, 256,
            eWi0 + (size_t)dir * G4 * 256, 256,
            eb0 + dir * G4,
            Gx + (size_t)dir * TB * G4, G4);
    }
    enc_persist_kernel<<<dim3(129, 2), 256>>>(Gx, eWh0, eh, ec, out0);
    copy2_kernel<<<(S2 + 255) / 256, 256>>>(eh, ec, dh, dc, S2);

    // ---- encoder layer 1 ----
    zero_kernel<<<(S2 + 255) / 256, 256>>>(eh, S2);
    zero_kernel<<<(S2 + 255) / 256, 256>>>(ec, S2);
    for (int dir = 0; dir < 2; dir++) {
        sgemm_nt_kernel<<<dim3((G4 + 127) / 128, TB / 128), 256>>>(
            TB, G4, H2, out0, H2,
            eWi1 + (size_t)dir * G4 * H2, H2,
            eb1 + dir * G4,
            Gx + (size_t)dir * TB * G4, G4);
    }
    enc_persist_kernel<<<dim3(129, 2), 256>>>(Gx, eWh1, eh, ec, outenc);
    copy2_kernel<<<(S2 + 255) / 256, 256>>>(eh, ec, dh + S2, dc + S2, S2);

    // ---- attention precompute: E2 = outenc @ attn_W[:,1032:]^T + attn_b ----
    sgemm_nt_kernel<<<dim3((H2 + 127) / 128, TB / 128), 256>>>(
        TB, H2, H2, outenc, H2,
        attn_W + H2, G4,
        attn_b, E2, H2);

    // ---- decoder loop ----
    for (int ts = 0; ts < NY; ts++) {
        int pp = (ts & 1) * S4, np = ((ts + 1) & 1) * S4;
        dec_cell_kernel<<<dim3(129, 2), 256>>>(
            y + (size_t)ts * B * SEQ, SEQ, dWi0, dWh0, db0,
            dh + pp, dh + np, dc + pp, dc + np, l0, H2);
        dec_cell_kernel<<<dim3(129, 2), 256>>>(
            l0, H2, dWi1, dWh1, db1,
            dh + pp + S2, dh + np + S2, dc + pp + S2, dc + np + S2,
            cc, 2 * H2);
        skinny64_nt_kernel<<<(H2 + 15) / 16, 256>>>(
            H2, H2, cc, 2 * H2, attn_W, G4, nullptr, dbuf, H2, 0);
        score_kernel<<<TB / 8, 256>>>(E2, dbuf, attn_v, score);
        attn_kernel<<<B, 512>>>(score, outenc, cc);
        skinny64_nt_kernel<<<(H2 + 15) / 16, 256>>>(
            H2, G4, cc, 2 * H2, concat_W, G4, concat_b, co, H2, 1);
        ce_fused_kernel<<<1, 1024>>>(co, out_W, out_b, label + ts * B, loss);
    }

    write_out_kernel<<<1, 1>>>((float*)d_out, loss);
}

// round 10
// speedup vs baseline: 1.1000x; 1.1000x over previous
#include <cuda_runtime.h>
#include <math.h>
#include <stdint.h>

// Problem constants
#define H   516
#define T   512
#define B   64
#define NY  20
#define SEQ 20
#define G4  2064      /* 4*H */
#define H2  1032      /* 2*H */
#define TB  32768     /* T*B */

// ------------------------- scratch (device globals) -------------------------
__device__ float g_xe[TB * 256];
__device__ float g_Gx[TB * 2 * G4];         // [t*B+b][dir*G4 + j]  (interleaved)
__device__ float g_out0[TB * H2];
__device__ float g_outenc[TB * H2];
__device__ float g_E2[TB * H2];
__device__ float g_eh[2 * 2 * B * H];       // [parity][dir][B][H]
__device__ float g_ec[2 * 2 * B * H];
__device__ float g_dh[2 * 4 * B * H];       // [parity][slot4][B][H]
__device__ float g_dc[2 * 4 * B * H];
__device__ float g_l0[B * H2];
__device__ float g_cc[B * 2 * H2];          // [outdec | context]
__device__ float g_dbuf[B * H2];
__device__ float g_co[B * H2];
__device__ float g_score[B * T];
__device__ float g_loss[1];
__device__ unsigned g_bcount = 0;
__device__ unsigned g_bgen = 0;

// --------------------------- packed helpers ---------------------------------
__device__ __forceinline__ void fma2(unsigned long long& d,
                                     unsigned long long a,
                                     unsigned long long b) {
    asm("fma.rn.f32x2 %0, %1, %2, %0;" : "+l"(d) : "l"(a), "l"(b));
}
__device__ __forceinline__ unsigned long long pack2(float lo, float hi) {
    unsigned long long r;
    asm("mov.b64 %0, {%1, %2};" : "=l"(r) : "f"(lo), "f"(hi));
    return r;
}
__device__ __forceinline__ void unpack2(unsigned long long v, float& lo, float& hi) {
    asm("mov.b64 {%0, %1}, %2;" : "=f"(lo), "=f"(hi) : "l"(v));
}
__device__ __forceinline__ uint32_t to_tf32(float x) {
    uint32_t r;
    asm("cvt.rna.tf32.f32 %0, %1;" : "=r"(r) : "f"(x));
    return r;
}

// -------------------------- software grid barrier ---------------------------
__device__ __forceinline__ void grid_barrier(unsigned nb) {
    __syncthreads();
    if (threadIdx.x == 0) {
        __threadfence();
        unsigned gen = *(volatile unsigned*)&g_bgen;
        if (atomicAdd(&g_bcount, 1) == nb - 1) {
            atomicExch(&g_bcount, 0);
            __threadfence();
            atomicAdd(&g_bgen, 1);
        } else {
            while (*(volatile unsigned*)&g_bgen == gen) {}
        }
        __threadfence();
    }
    __syncthreads();
}

// ------------------------------ small kernels -------------------------------
__global__ void zero_kernel(float* p, int n) {
    int i = blockIdx.x * 256 + threadIdx.x;
    if (i < n) p[i] = 0.f;
}

__global__ void write_out_kernel(float* out, const float* loss) {
    out[0] = loss[0];
}

__global__ void copy2_kernel(const float* sh, const float* sc,
                             float* dh, float* dc, int n) {
    int i = blockIdx.x * 256 + threadIdx.x;
    if (i < n) { dh[i] = sh[i]; dc[i] = sc[i]; }
}

__global__ void expand_kernel(const float* __restrict__ x,
                              const float* __restrict__ We,
                              const float* __restrict__ be,
                              float* __restrict__ xe) {
    int row = blockIdx.x;
    int c = threadIdx.x;
    const float* xr = x + row * 4;
    const float* w = We + c * 4;
    xe[(size_t)row * 256 + c] =
        be[c] + xr[0] * w[0] + xr[1] * w[1] + xr[2] * w[2] + xr[3] * w[3];
}

// ---------------- TF32 tensor-core GEMM: C = A @ Bm^T + bias ----------------
// A:[M,K] row-major(lda), Bm:[N,K] row-major(ldb), C:[M,N](ldc).
// M % 128 == 0. K, N arbitrary (zero-padded / guarded).
// 256 threads = 8 warps (2 m x 4 n), warp tile 64x32, mma m16n8k8.
__global__ void __launch_bounds__(256, 2)
mma_nt_kernel(int M, int N, int K,
              const float* __restrict__ A, int lda,
              const float* __restrict__ Bm, int ldb,
              const float* __restrict__ bias,
              float* __restrict__ C, int ldc) {
    __shared__ uint32_t As[2][16][132];   // [buf][k][m]
    __shared__ uint32_t Bs[2][16][132];   // [buf][k][n]
    const int tid = threadIdx.x;
    const int lane = tid & 31, warp = tid >> 5;
    const int gid = lane >> 2, qid = lane & 3;
    const int wm = (warp & 1) * 64;
    const int wn = (warp >> 1) * 32;
    const int row0 = blockIdx.y * 128, col0 = blockIdx.x * 128;

    float acc[4][4][4];
#pragma unroll
    for (int mt = 0; mt < 4; mt++)
#pragma unroll
        for (int nt = 0; nt < 4; nt++)
#pragma unroll
            for (int i = 0; i < 4; i++) acc[mt][nt][i] = 0.f;

    const int nk = (K + 15) / 16;
    float4 stA[2], stB[2];

    auto LOADG = [&](int ch) {
        int k0 = ch * 16;
#pragma unroll
        for (int i = 0; i < 2; i++) {
            int q = tid * 2 + i;
            int r = q >> 2, c = (q & 3) * 4;
            // A tile (rows always valid)
            if (k0 + c + 3 < K) {
                stA[i] = *(const float4*)(A + (size_t)(row0 + r) * lda + k0 + c);
            } else {
                float tmp[4];
#pragma unroll
                for (int j = 0; j < 4; j++)
                    tmp[j] = (k0 + c + j < K)
                                 ? A[(size_t)(row0 + r) * lda + k0 + c + j] : 0.f;
                stA[i] = *(float4*)tmp;
            }
            // B tile (row = output col, guarded)
            int n = col0 + r;
            if (n < N && k0 + c + 3 < K) {
                stB[i] = *(const float4*)(Bm + (size_t)n * ldb + k0 + c);
            } else {
                float tmp[4];
#pragma unroll
                for (int j = 0; j < 4; j++)
                    tmp[j] = (n < N && k0 + c + j < K)
                                 ? Bm[(size_t)n * ldb + k0 + c + j] : 0.f;
                stB[i] = *(float4*)tmp;
            }
        }
    };

    auto STORE = [&](int buf) {
#pragma unroll
        for (int i = 0; i < 2; i++) {
            int q = tid * 2 + i;
            int r = q >> 2, c = (q & 3) * 4;
            const float* va = (const float*)&stA[i];
            const float* vb = (const float*)&stB[i];
#pragma unroll
            for (int j = 0; j < 4; j++) {
                As[buf][c + j][r] = to_tf32(va[j]);
                Bs[buf][c + j][r] = to_tf32(vb[j]);
            }
        }
    };

    auto COMPUTE = [&](int buf) {
#pragma unroll
        for (int ks = 0; ks < 2; ks++) {
            const int kb = ks * 8 + qid;
            uint32_t af[4][4], bf[4][2];
#pragma unroll
            for (int mt = 0; mt < 4; mt++) {
                int m0 = wm + mt * 16 + gid;
                af[mt][0] = As[buf][kb][m0];
                af[mt][1] = As[buf][kb][m0 + 8];
                af[mt][2] = As[buf][kb + 4][m0];
                af[mt][3] = As[buf][kb + 4][m0 + 8];
            }
#pragma unroll
            for (int nt = 0; nt < 4; nt++) {
                int n0 = wn + nt * 8 + gid;
                bf[nt][0] = Bs[buf][kb][n0];
                bf[nt][1] = Bs[buf][kb + 4][n0];
            }
#pragma unroll
            for (int mt = 0; mt < 4; mt++)
#pragma unroll
                for (int nt = 0; nt < 4; nt++) {
                    asm volatile(
                        "mma.sync.aligned.m16n8k8.row.col.f32.tf32.tf32.f32 "
                        "{%0,%1,%2,%3}, {%4,%5,%6,%7}, {%8,%9}, {%0,%1,%2,%3};"
                        : "+f"(acc[mt][nt][0]), "+f"(acc[mt][nt][1]),
                          "+f"(acc[mt][nt][2]), "+f"(acc[mt][nt][3])
                        : "r"(af[mt][0]), "r"(af[mt][1]),
                          "r"(af[mt][2]), "r"(af[mt][3]),
                          "r"(bf[nt][0]), "r"(bf[nt][1]));
                }
        }
    };

    LOADG(0);
    STORE(0);
    __syncthreads();
    for (int ch = 0; ch < nk; ch++) {
        if (ch + 1 < nk) LOADG(ch + 1);
        COMPUTE(ch & 1);
        if (ch + 1 < nk) STORE((ch + 1) & 1);
        __syncthreads();
    }

    // writeback
#pragma unroll
    for (int mt = 0; mt < 4; mt++) {
        int r1 = row0 + wm + mt * 16 + gid;
#pragma unroll
        for (int nt = 0; nt < 4; nt++) {
            int c0 = col0 + wn + nt * 8 + qid * 2;
            float b0 = 0.f, b1 = 0.f;
            if (bias) {
                if (c0 < N) b0 = bias[c0];
                if (c0 + 1 < N) b1 = bias[c0 + 1];
            }
            if (c0 < N) {
                C[(size_t)r1 * ldc + c0] = acc[mt][nt][0] + b0;
                C[(size_t)(r1 + 8) * ldc + c0] = acc[mt][nt][2] + b0;
            }
            if (c0 + 1 < N) {
                C[(size_t)r1 * ldc + c0 + 1] = acc[mt][nt][1] + b1;
                C[(size_t)(r1 + 8) * ldc + c0 + 1] = acc[mt][nt][3] + b1;
            }
        }
    }
}

// ------------- persistent encoder layer: all T steps in one launch ----------
// grid (129, 2 dirs), 256 threads, co-resident (launch_bounds 256,2).
__global__ void __launch_bounds__(256, 2)
enc_persist_kernel(const float* __restrict__ Gx,   // [t*B+b][2*G4] interleaved
                   const float* __restrict__ Wh,   // [2][G4][H]
                   float* __restrict__ h,          // [2 parity][2 dir][B][H]
                   float* __restrict__ c,
                   float* __restrict__ outseq) {   // [T][B][H2]
    const int dir = blockIdx.y;
    const int j0 = blockIdx.x * 4;
    const int tid = threadIdx.x;
    const int tx = tid & 15, ty = tid >> 4, rb = ty * 4;
    const unsigned nb = gridDim.x * gridDim.y;

    __shared__ float Wsf[16][517];
    __shared__ float As[2][12][68];
    __shared__ float gsm[64][17];

    const float* whd = Wh + (size_t)dir * G4 * H;
    for (int idx = tid; idx < 16 * H; idx += 256) {
        int r = idx / H, k = idx % H;
        int rq = r >> 2, ru = r & 3;
        Wsf[r][k] = whd[(size_t)(rq * H + j0 + ru) * H + k];
    }
    __syncthreads();

    const int SBH_ = B * H, S2_ = 2 * SBH_;
    const int eb0 = tid / 12,         ek0 = tid % 12;
    const int eb1 = (tid + 256) / 12, ek1 = (tid + 256) % 12;
    const int eb2 = (tid + 512) / 12, ek2 = (tid + 512) % 12;

    for (int s = 0; s < T; s++) {
        const int t = dir ? (T - 1 - s) : s;
        const float* hp = h + (s & 1) * S2_ + dir * SBH_;
        float* hn = h + ((s + 1) & 1) * S2_ + dir * SBH_;
        const float* cp_ = c + (s & 1) * S2_ + dir * SBH_;
        float* cn_ = c + ((s + 1) & 1) * S2_ + dir * SBH_;

        As[0][ek0][eb0] = hp[eb0 * H + ek0];
        As[0][ek1][eb1] = hp[eb1 * H + ek1];
        As[0][ek2][eb2] = hp[eb2 * H + ek2];
        __syncthreads();

        unsigned long long acc01 = 0ull, acc23 = 0ull;
        for (int kc = 0; kc < 43; kc++) {     // 516 = 43*12
            const int buf = kc & 1;
            float pf0 = 0.f, pf1 = 0.f, pf2 = 0.f;
            if (kc < 42) {
                int base = (kc + 1) * 12;
                pf0 = hp[eb0 * H + base + ek0];
                pf1 = hp[eb1 * H + base + ek1];
                pf2 = hp[eb2 * H + base + ek2];
            }
#pragma unroll
            for (int kk = 0; kk < 12; kk++) {
                const unsigned long long* h2 =
                    (const unsigned long long*)&As[buf][kk][rb];
                unsigned long long h01 = h2[0], h23 = h2[1];
                float w = Wsf[tx][kc * 12 + kk];
                unsigned long long wp = pack2(w, w);
                fma2(acc01, wp, h01);
                fma2(acc23, wp, h23);
            }
            if (kc < 42) {
                As[buf ^ 1][ek0][eb0] = pf0;
                As[buf ^ 1][ek1][eb1] = pf1;
                As[buf ^ 1][ek2][eb2] = pf2;
            }
            __syncthreads();
        }

        float a0, a1, a2, a3;
        unpack2(acc01, a0, a1);
        unpack2(acc23, a2, a3);
        gsm[rb + 0][tx] = a0; gsm[rb + 1][tx] = a1;
        gsm[rb + 2][tx] = a2; gsm[rb + 3][tx] = a3;
        __syncthreads();

        {
            int bb = tid >> 2, uu = tid & 3;
            int j = j0 + uu;
            const float* gx = Gx + ((size_t)t * B + bb) * (2 * G4) + dir * G4 + j;
            float gi = gsm[bb][uu]      + gx[0];
            float gf = gsm[bb][4 + uu]  + gx[H];
            float gg = gsm[bb][8 + uu]  + gx[2 * H];
            float go = gsm[bb][12 + uu] + gx[3 * H];
            float cp = cp_[bb * H + j];
            float si = 1.f / (1.f + expf(-gi));
            float sf = 1.f / (1.f + expf(-gf));
            float so = 1.f / (1.f + expf(-go));
            float cn = fmaf(sf, cp, si * tanhf(gg));
            float hn_ = so * tanhf(cn);
            cn_[bb * H + j] = cn;
            hn[bb * H + j] = hn_;
            outseq[((size_t)t * B + bb) * H2 + dir * H + j] = hn_;
        }
        if (s < T - 1) grid_barrier(nb);
    }
}

// ------------------------- decoder LSTM cell (1 step) -----------------------
__global__ void dec_cell_kernel(const float* __restrict__ x, int Kx,
                                const float* __restrict__ Wi,
                                const float* __restrict__ Wh,
                                const float* __restrict__ bias,
                                const float* __restrict__ hprev, float* __restrict__ hnext,
                                const float* __restrict__ cprev, float* __restrict__ cnext,
                                float* __restrict__ outcat, int outld) {
    const int dir = blockIdx.y;
    const int j0 = blockIdx.x * 4;
    const int tid = threadIdx.x;
    const int tx = tid & 15, ty = tid >> 4, rb = ty * 4;

    __shared__ float As[12][68];
    __shared__ float Ws[16][13];
    __shared__ float gsm[64][17];

    float acc0 = 0.f, acc1 = 0.f, acc2 = 0.f, acc3 = 0.f;

    for (int ph = 0; ph < 2; ph++) {
        const float* A = (ph == 0) ? x : (hprev + dir * (B * H));
        const int K = (ph == 0) ? Kx : H;
        const float* W = (ph == 0) ? (Wi + (size_t)dir * G4 * Kx)
                                   : (Wh + (size_t)dir * G4 * H);
        for (int k0 = 0; k0 < K; k0 += 12) {
            int rem = K - k0; if (rem > 12) rem = 12;
            for (int idx = tid; idx < 64 * 12; idx += 256) {
                int bb = idx / 12, kk = idx % 12;
                As[kk][bb] = (kk < rem) ? A[bb * K + k0 + kk] : 0.f;
            }
            if (tid < 192) {
                int r = tid / 12, kk = tid % 12;
                int rq = r >> 2, ru = r & 3;
                float wv = 0.f;
                if (kk < rem)
                    wv = W[(size_t)(rq * H + j0 + ru) * K + k0 + kk];
                Ws[r][kk] = wv;
            }
            __syncthreads();
#pragma unroll
            for (int kk = 0; kk < 12; kk++) {
                float4 hv = *(const float4*)&As[kk][rb];
                float w = Ws[tx][kk];
                acc0 = fmaf(hv.x, w, acc0);
                acc1 = fmaf(hv.y, w, acc1);
                acc2 = fmaf(hv.z, w, acc2);
                acc3 = fmaf(hv.w, w, acc3);
            }
            __syncthreads();
        }
    }

    gsm[rb + 0][tx] = acc0; gsm[rb + 1][tx] = acc1;
    gsm[rb + 2][tx] = acc2; gsm[rb + 3][tx] = acc3;
    __syncthreads();

    {
        int bb = tid >> 2, uu = tid & 3;
        int j = j0 + uu;
        const float* bz = bias + dir * G4;
        float gi = gsm[bb][uu]      + bz[j];
        float gf = gsm[bb][4 + uu]  + bz[H + j];
        float gg = gsm[bb][8 + uu]  + bz[2 * H + j];
        float go = gsm[bb][12 + uu] + bz[3 * H + j];
        float cp = cprev[dir * B * H + bb * H + j];
        float si = 1.f / (1.f + expf(-gi));
        float sf = 1.f / (1.f + expf(-gf));
        float so = 1.f / (1.f + expf(-go));
        float cn = fmaf(sf, cp, si * tanhf(gg));
        float hn = so * tanhf(cn);
        cnext[dir * B * H + bb * H + j] = cn;
        hnext[dir * B * H + bb * H + j] = hn;
        outcat[bb * outld + dir * H + j] = hn;
    }
}

// -------------------- skinny GEMM: C[64,N] = A@W^T (+b, tanh) ---------------
__global__ void skinny64_nt_kernel(int N, int K,
                                   const float* __restrict__ A, int lda,
                                   const float* __restrict__ W, int ldw,
                                   const float* __restrict__ bias,
                                   float* __restrict__ C, int ldc, int act) {
    __shared__ float As[16][68];
    __shared__ float Ws[16][17];
    const int tid = threadIdx.x;
    const int tx = tid & 15, ty = tid >> 4;
    const int col = blockIdx.x * 16 + tx;

    float acc[4] = {0.f, 0.f, 0.f, 0.f};

    for (int k0 = 0; k0 < K; k0 += 16) {
        for (int idx = tid; idx < 64 * 16; idx += 256) {
            int r = idx >> 4, kk = idx & 15;
            As[kk][r] = (k0 + kk < K) ? A[(size_t)r * lda + k0 + kk] : 0.f;
        }
        {
            int cix = tid & 15, kk = tid >> 4;
            int cg = blockIdx.x * 16 + cix;
            float wv = 0.f;
            if (cg < N && (k0 + kk) < K)
                wv = W[(size_t)cg * ldw + k0 + kk];
            Ws[cix][kk] = wv;
        }
        __syncthreads();
#pragma unroll
        for (int kk = 0; kk < 16; kk++) {
            float w = Ws[tx][kk];
            float4 a = *(const float4*)&As[kk][ty * 4];
            acc[0] = fmaf(a.x, w, acc[0]);
            acc[1] = fmaf(a.y, w, acc[1]);
            acc[2] = fmaf(a.z, w, acc[2]);
            acc[3] = fmaf(a.w, w, acc[3]);
        }
        __syncthreads();
    }

    if (col < N) {
#pragma unroll
        for (int i = 0; i < 4; i++) {
            int r = ty * 4 + i;
            float v = acc[i];
            if (bias) v += bias[col];
            if (act) v = tanhf(v);
            C[(size_t)r * ldc + col] = v;
        }
    }
}

// ------------------------------ attention ----------------------------------
__global__ void score_kernel(const float* __restrict__ E2,
                             const float* __restrict__ dbuf,
                             const float* __restrict__ v,
                             float* __restrict__ score) {
    int w = blockIdx.x * 8 + (threadIdx.x >> 5);
    int lane = threadIdx.x & 31;
    int bb = w & 63, t = w >> 6;
    const float* e = E2 + (size_t)w * H2;
    const float* d = dbuf + bb * H2;
    float s = 0.f;
    for (int hh = lane; hh < H2; hh += 32)
        s += v[hh] * tanhf(e[hh] + d[hh]);
#pragma unroll
    for (int o = 16; o > 0; o >>= 1)
        s += __shfl_down_sync(0xffffffffu, s, o);
    if (lane == 0) score[bb * T + t] = s;
}

// fused softmax over T + context accumulation. block = b, 512 threads.
__global__ void attn_kernel(const float* __restrict__ score,
                            const float* __restrict__ enc,
                            float* __restrict__ cc) {
    __shared__ float sm[T];
    __shared__ float aws[T];
    int bb = blockIdx.x, tid = threadIdx.x;
    float v = score[bb * T + tid];
    sm[tid] = v;
    __syncthreads();
    for (int st = 256; st > 0; st >>= 1) {
        if (tid < st) sm[tid] = fmaxf(sm[tid], sm[tid + st]);
        __syncthreads();
    }
    float mx = sm[0];
    __syncthreads();
    float e = expf(v - mx);
    sm[tid] = e;
    __syncthreads();
    for (int st = 256; st > 0; st >>= 1) {
        if (tid < st) sm[tid] += sm[tid + st];
        __syncthreads();
    }
    aws[tid] = e / sm[0];
    __syncthreads();

    float acc[3] = {0.f, 0.f, 0.f};
    for (int t = 0; t < T; t++) {
        float wt = aws[t];
        const float* ep = enc + ((size_t)t * B + bb) * H2;
#pragma unroll
        for (int j = 0; j < 3; j++) {
            int hh = tid + j * 512;
            if (hh < H2) acc[j] = fmaf(wt, ep[hh], acc[j]);
        }
    }
#pragma unroll
    for (int j = 0; j < 3; j++) {
        int hh = tid + j * 512;
        if (hh < H2) cc[bb * (2 * H2) + H2 + hh] = acc[j];
    }
}

// -------------- fused logits + cross-entropy (single block, det.) -----------
__global__ void ce_fused_kernel(const float* __restrict__ co,
                                const float* __restrict__ out_W,
                                const float* __restrict__ out_b,
                                const int* __restrict__ lab,
                                float* __restrict__ loss) {
    __shared__ float lg[64][20];
    __shared__ float red[64];
    int tid = threadIdx.x;           // 1024 threads
    int bb = tid >> 4, slot = tid & 15;
    for (int cix = slot; cix < SEQ; cix += 16) {
        const float* a = co + bb * H2;
        const float* w = out_W + cix * H2;
        float s = out_b[cix];
#pragma unroll 4
        for (int k = 0; k < H2; k++) s = fmaf(a[k], w[k], s);
        lg[bb][cix] = s;
    }
    __syncthreads();
    if (slot == 0) {
        float m = lg[bb][0];
#pragma unroll
        for (int i = 1; i < SEQ; i++) m = fmaxf(m, lg[bb][i]);
        float s = 0.f;
#pragma unroll
        for (int i = 0; i < SEQ; i++) s += expf(lg[bb][i] - m);
        red[bb] = -(lg[bb][lab[bb]] - m - logf(s));
    }
    __syncthreads();
    if (tid == 0) {
        float tot = 0.f;
        for (int i = 0; i < 64; i++) tot += red[i];
        loss[0] += tot / 64.f;
    }
}

// ------------------------------- host --------------------------------------
static float* symaddr(const void* devsym) {
    void* p = nullptr;
    cudaGetSymbolAddress(&p, devsym);
    return (float*)p;
}

extern "C" void kernel_launch(void* const* d_in, const int* in_sizes, int n_in,
                              void* d_out, int out_size) {
    (void)in_sizes; (void)n_in; (void)out_size;
    const float* x        = (const float*)d_in[0];
    const float* y        = (const float*)d_in[1];
    const int*   label    = (const int*)d_in[2];
    const float* expand_W = (const float*)d_in[3];
    const float* expand_b = (const float*)d_in[4];
    const float* eWi0     = (const float*)d_in[5];
    const float* eWh0     = (const float*)d_in[6];
    const float* eb0      = (const float*)d_in[7];
    const float* eWi1     = (const float*)d_in[8];
    const float* eWh1     = (const float*)d_in[9];
    const float* eb1      = (const float*)d_in[10];
    const float* dWi0     = (const float*)d_in[11];
    const float* dWh0     = (const float*)d_in[12];
    const float* db0      = (const float*)d_in[13];
    const float* dWi1     = (const float*)d_in[14];
    const float* dWh1     = (const float*)d_in[15];
    const float* db1      = (const float*)d_in[16];
    const float* attn_W   = (const float*)d_in[17];
    const float* attn_b   = (const float*)d_in[18];
    const float* attn_v   = (const float*)d_in[19];
    const float* concat_W = (const float*)d_in[20];
    const float* concat_b = (const float*)d_in[21];
    const float* out_W    = (const float*)d_in[22];
    const float* out_b    = (const float*)d_in[23];

    float* xe     = symaddr(&g_xe);
    float* Gx     = symaddr(&g_Gx);
    float* out0   = symaddr(&g_out0);
    float* outenc = symaddr(&g_outenc);
    float* E2     = symaddr(&g_E2);
    float* eh     = symaddr(&g_eh);
    float* ec     = symaddr(&g_ec);
    float* dh     = symaddr(&g_dh);
    float* dc     = symaddr(&g_dc);
    float* l0     = symaddr(&g_l0);
    float* cc     = symaddr(&g_cc);
    float* dbuf   = symaddr(&g_dbuf);
    float* co     = symaddr(&g_co);
    float* score  = symaddr(&g_score);
    float* loss   = symaddr(&g_loss);

    const int SBH = B * H;
    const int S2  = 2 * SBH;
    const int S4  = 4 * SBH;

    zero_kernel<<<1, 32>>>(loss, 1);
    zero_kernel<<<(S2 + 255) / 256, 256>>>(eh, S2);
    zero_kernel<<<(S2 + 255) / 256, 256>>>(ec, S2);

    expand_kernel<<<TB, 256>>>(x, expand_W, expand_b, xe);

    // ---- encoder layer 0: Gx = xe @ [Wi_f | Wi_b]^T + b (both dirs fused) ----
    mma_nt_kernel<<<dim3((2 * G4 + 127) / 128, TB / 128), 256>>>(
        TB, 2 * G4, 256, xe, 256, eWi0, 256, eb0, Gx, 2 * G4);
    enc_persist_kernel<<<dim3(129, 2), 256>>>(Gx, eWh0, eh, ec, out0);
    copy2_kernel<<<(S2 + 255) / 256, 256>>>(eh, ec, dh, dc, S2);

    // ---- encoder layer 1 ----
    zero_kernel<<<(S2 + 255) / 256, 256>>>(eh, S2);
    zero_kernel<<<(S2 + 255) / 256, 256>>>(ec, S2);
    mma_nt_kernel<<<dim3((2 * G4 + 127) / 128, TB / 128), 256>>>(
        TB, 2 * G4, H2, out0, H2, eWi1, H2, eb1, Gx, 2 * G4);
    enc_persist_kernel<<<dim3(129, 2), 256>>>(Gx, eWh1, eh, ec, outenc);
    copy2_kernel<<<(S2 + 255) / 256, 256>>>(eh, ec, dh + S2, dc + S2, S2);

    // ---- attention precompute: E2 = outenc @ attn_W[:,1032:]^T + attn_b ----
    mma_nt_kernel<<<dim3((H2 + 127) / 128, TB / 128), 256>>>(
        TB, H2, H2, outenc, H2, attn_W + H2, G4, attn_b, E2, H2);

    // ---- decoder loop ----
    for (int ts = 0; ts < NY; ts++) {
        int pp = (ts & 1) * S4, np = ((ts + 1) & 1) * S4;
        dec_cell_kernel<<<dim3(129, 2), 256>>>(
            y + (size_t)ts * B * SEQ, SEQ, dWi0, dWh0, db0,
            dh + pp, dh + np, dc + pp, dc + np, l0, H2);
        dec_cell_kernel<<<dim3(129, 2), 256>>>(
            l0, H2, dWi1, dWh1, db1,
            dh + pp + S2, dh + np + S2, dc + pp + S2, dc + np + S2,
            cc, 2 * H2);
        skinny64_nt_kernel<<<(H2 + 15) / 16, 256>>>(
            H2, H2, cc, 2 * H2, attn_W, G4, nullptr, dbuf, H2, 0);
        score_kernel<<<TB / 8, 256>>>(E2, dbuf, attn_v, score);
        attn_kernel<<<B, 512>>>(score, outenc, cc);
        skinny64_nt_kernel<<<(H2 + 15) / 16, 256>>>(
            H2, G4, cc, 2 * H2, concat_W, G4, concat_b, co, H2, 1);
        ce_fused_kernel<<<1, 1024>>>(co, out_W, out_b, label + ts * B, loss);
    }

    write_out_kernel<<<1, 1>>>((float*)d_out, loss);
}

// round 11
// speedup vs baseline: 1.1114x; 1.0103x over previous
#include <cuda_runtime.h>
#include <math.h>
#include <stdint.h>

// Problem constants
#define H   516
#define T   512
#define B   64
#define NY  20
#define SEQ 20
#define G4  2064      /* 4*H */
#define H2  1032      /* 2*H */
#define TB  32768     /* T*B */
#define G8  4128      /* 2*G4 */

// ------------------------- scratch (device globals) -------------------------
__device__ float g_Gx[TB * G8];             // [t*B+b][dir*G4 + j]  (interleaved)
__device__ float g_out0[TB * H2];
__device__ float g_outenc[TB * H2];
__device__ float g_E2[TB * H2];
__device__ float g_Wc[G8 * 4];              // folded layer0 input weights
__device__ float g_bc[G8];                  // folded layer0 bias
__device__ float g_eh[2 * 2 * B * H];       // [parity][dir][B][H]
__device__ float g_ec[2 * 2 * B * H];
__device__ float g_dh[2 * 4 * B * H];       // [parity][slot4][B][H]
__device__ float g_dc[2 * 4 * B * H];
__device__ float g_l0[B * H2];
__device__ float g_cc[B * 2 * H2];          // [outdec | context]
__device__ float g_dbuf[B * H2];
__device__ float g_co[B * H2];
__device__ float g_score[B * T];
__device__ float g_loss[1];
__device__ unsigned g_bcount = 0;
__device__ unsigned g_bgen = 0;

// --------------------------- packed helpers ---------------------------------
__device__ __forceinline__ void fma2(unsigned long long& d,
                                     unsigned long long a,
                                     unsigned long long b) {
    asm("fma.rn.f32x2 %0, %1, %2, %0;" : "+l"(d) : "l"(a), "l"(b));
}
__device__ __forceinline__ unsigned long long pack2(float lo, float hi) {
    unsigned long long r;
    asm("mov.b64 %0, {%1, %2};" : "=l"(r) : "f"(lo), "f"(hi));
    return r;
}
__device__ __forceinline__ void unpack2(unsigned long long v, float& lo, float& hi) {
    asm("mov.b64 {%0, %1}, %2;" : "=f"(lo), "=f"(hi) : "l"(v));
}
__device__ __forceinline__ uint32_t to_tf32(float x) {
    uint32_t r;
    asm("cvt.rna.tf32.f32 %0, %1;" : "=r"(r) : "f"(x));
    return r;
}
__device__ __forceinline__ float ftanh(float x) {
    float r;
    asm("tanh.approx.f32 %0, %1;" : "=f"(r) : "f"(x));
    return r;
}

// -------------------------- software grid barrier ---------------------------
__device__ __forceinline__ void grid_barrier(unsigned nb) {
    __syncthreads();
    if (threadIdx.x == 0) {
        __threadfence();
        unsigned gen = *(volatile unsigned*)&g_bgen;
        if (atomicAdd(&g_bcount, 1) == nb - 1) {
            atomicExch(&g_bcount, 0);
            __threadfence();
            atomicAdd(&g_bgen, 1);
        } else {
            while (*(volatile unsigned*)&g_bgen == gen) {}
        }
        __threadfence();
    }
    __syncthreads();
}

// ------------------------------ small kernels -------------------------------
__global__ void zero_kernel(float* p, int n) {
    int i = blockIdx.x * 256 + threadIdx.x;
    if (i < n) p[i] = 0.f;
}

__global__ void write_out_kernel(float* out, const float* loss) {
    out[0] = loss[0];
}

__global__ void copy2_kernel(const float* sh, const float* sc,
                             float* dh, float* dc, int n) {
    int i = blockIdx.x * 256 + threadIdx.x;
    if (i < n) { dh[i] = sh[i]; dc[i] = sc[i]; }
}

// Wc = eWi0 @ expand_W  (G8 x 4), bc = eWi0 @ expand_b + eb0
__global__ void fold0_kernel(const float* __restrict__ eWi0,   // [G8][256]
                             const float* __restrict__ We,     // [256][4]
                             const float* __restrict__ be,     // [256]
                             const float* __restrict__ eb0,    // [G8]
                             float* __restrict__ Wc,
                             float* __restrict__ bc) {
    int i = blockIdx.x * 128 + threadIdx.x;
    if (i >= G8) return;
    const float* wi = eWi0 + (size_t)i * 256;
    float a0 = 0.f, a1 = 0.f, a2 = 0.f, a3 = 0.f, ab = eb0[i];
    for (int k = 0; k < 256; k++) {
        float w = wi[k];
        float4 we4 = *(const float4*)(We + k * 4);
        a0 = fmaf(w, we4.x, a0);
        a1 = fmaf(w, we4.y, a1);
        a2 = fmaf(w, we4.z, a2);
        a3 = fmaf(w, we4.w, a3);
        ab = fmaf(w, be[k], ab);
    }
    *(float4*)(Wc + (size_t)i * 4) = make_float4(a0, a1, a2, a3);
    bc[i] = ab;
}

// Gx = x @ Wc^T + bc   (K = 4). grid (33, TB/64), 256 threads.
__global__ void gx0_kernel(const float* __restrict__ x,      // [TB][4]
                           const float* __restrict__ Wc,     // [G8][4]
                           const float* __restrict__ bc,     // [G8]
                           float* __restrict__ Gx) {         // [TB][G8]
    __shared__ float4 xs[64];
    __shared__ float4 ws[128];
    __shared__ float bs[128];
    int tid = threadIdx.x;
    int r0 = blockIdx.y * 64, c0 = blockIdx.x * 128;
    if (tid < 64) xs[tid] = *(const float4*)(x + (size_t)(r0 + tid) * 4);
    if (tid >= 128) {
        int q = tid - 128;
        int c = c0 + q;
        if (c < G8) {
            ws[q] = *(const float4*)(Wc + (size_t)c * 4);
            bs[q] = bc[c];
        } else {
            ws[q] = make_float4(0.f, 0.f, 0.f, 0.f);
            bs[q] = 0.f;
        }
    }
    __syncthreads();
    int tc = (tid & 31) * 4;     // local col group
    int tr = (tid >> 5) * 8;     // local row base
    int cg = c0 + tc;
    if (cg >= G8) return;
    float4 w0 = ws[tc], w1 = ws[tc + 1], w2 = ws[tc + 2], w3 = ws[tc + 3];
    float b0 = bs[tc], b1 = bs[tc + 1], b2 = bs[tc + 2], b3 = bs[tc + 3];
#pragma unroll
    for (int i = 0; i < 8; i++) {
        int r = r0 + tr + i;
        float4 xv = xs[tr + i];
        float4 o;
        o.x = fmaf(xv.x, w0.x, fmaf(xv.y, w0.y, fmaf(xv.z, w0.z, fmaf(xv.w, w0.w, b0))));
        o.y = fmaf(xv.x, w1.x, fmaf(xv.y, w1.y, fmaf(xv.z, w1.z, fmaf(xv.w, w1.w, b1))));
        o.z = fmaf(xv.x, w2.x, fmaf(xv.y, w2.y, fmaf(xv.z, w2.z, fmaf(xv.w, w2.w, b2))));
        o.w = fmaf(xv.x, w3.x, fmaf(xv.y, w3.y, fmaf(xv.z, w3.z, fmaf(xv.w, w3.w, b3))));
        *(float4*)(Gx + (size_t)r * G8 + cg) = o;
    }
}

// ---------------- TF32 tensor-core GEMM: C = A @ Bm^T + bias ----------------
__global__ void __launch_bounds__(256, 2)
mma_nt_kernel(int M, int N, int K,
              const float* __restrict__ A, int lda,
              const float* __restrict__ Bm, int ldb,
              const float* __restrict__ bias,
              float* __restrict__ C, int ldc) {
    __shared__ uint32_t As[2][16][132];   // [buf][k][m]
    __shared__ uint32_t Bs[2][16][132];   // [buf][k][n]
    const int tid = threadIdx.x;
    const int lane = tid & 31, warp = tid >> 5;
    const int gid = lane >> 2, qid = lane & 3;
    const int wm = (warp & 1) * 64;
    const int wn = (warp >> 1) * 32;
    const int row0 = blockIdx.y * 128, col0 = blockIdx.x * 128;

    float acc[4][4][4];
#pragma unroll
    for (int mt = 0; mt < 4; mt++)
#pragma unroll
        for (int nt = 0; nt < 4; nt++)
#pragma unroll
            for (int i = 0; i < 4; i++) acc[mt][nt][i] = 0.f;

    const int nk = (K + 15) / 16;
    float4 stA[2], stB[2];

    auto LOADG = [&](int ch) {
        int k0 = ch * 16;
#pragma unroll
        for (int i = 0; i < 2; i++) {
            int q = tid * 2 + i;
            int r = q >> 2, c = (q & 3) * 4;
            if (k0 + c + 3 < K) {
                stA[i] = *(const float4*)(A + (size_t)(row0 + r) * lda + k0 + c);
            } else {
                float tmp[4];
#pragma unroll
                for (int j = 0; j < 4; j++)
                    tmp[j] = (k0 + c + j < K)
                                 ? A[(size_t)(row0 + r) * lda + k0 + c + j] : 0.f;
                stA[i] = *(float4*)tmp;
            }
            int n = col0 + r;
            if (n < N && k0 + c + 3 < K) {
                stB[i] = *(const float4*)(Bm + (size_t)n * ldb + k0 + c);
            } else {
                float tmp[4];
#pragma unroll
                for (int j = 0; j < 4; j++)
                    tmp[j] = (n < N && k0 + c + j < K)
                                 ? Bm[(size_t)n * ldb + k0 + c + j] : 0.f;
                stB[i] = *(float4*)tmp;
            }
        }
    };

    auto STORE = [&](int buf) {
#pragma unroll
        for (int i = 0; i < 2; i++) {
            int q = tid * 2 + i;
            int r = q >> 2, c = (q & 3) * 4;
            const float* va = (const float*)&stA[i];
            const float* vb = (const float*)&stB[i];
#pragma unroll
            for (int j = 0; j < 4; j++) {
                As[buf][c + j][r] = to_tf32(va[j]);
                Bs[buf][c + j][r] = to_tf32(vb[j]);
            }
        }
    };

    auto COMPUTE = [&](int buf) {
#pragma unroll
        for (int ks = 0; ks < 2; ks++) {
            const int kb = ks * 8 + qid;
            uint32_t af[4][4], bf[4][2];
#pragma unroll
            for (int mt = 0; mt < 4; mt++) {
                int m0 = wm + mt * 16 + gid;
                af[mt][0] = As[buf][kb][m0];
                af[mt][1] = As[buf][kb][m0 + 8];
                af[mt][2] = As[buf][kb + 4][m0];
                af[mt][3] = As[buf][kb + 4][m0 + 8];
            }
#pragma unroll
            for (int nt = 0; nt < 4; nt++) {
                int n0 = wn + nt * 8 + gid;
                bf[nt][0] = Bs[buf][kb][n0];
                bf[nt][1] = Bs[buf][kb + 4][n0];
            }
#pragma unroll
            for (int mt = 0; mt < 4; mt++)
#pragma unroll
                for (int nt = 0; nt < 4; nt++) {
                    asm volatile(
                        "mma.sync.aligned.m16n8k8.row.col.f32.tf32.tf32.f32 "
                        "{%0,%1,%2,%3}, {%4,%5,%6,%7}, {%8,%9}, {%0,%1,%2,%3};"
                        : "+f"(acc[mt][nt][0]), "+f"(acc[mt][nt][1]),
                          "+f"(acc[mt][nt][2]), "+f"(acc[mt][nt][3])
                        : "r"(af[mt][0]), "r"(af[mt][1]),
                          "r"(af[mt][2]), "r"(af[mt][3]),
                          "r"(bf[nt][0]), "r"(bf[nt][1]));
                }
        }
    };

    LOADG(0);
    STORE(0);
    __syncthreads();
    for (int ch = 0; ch < nk; ch++) {
        if (ch + 1 < nk) LOADG(ch + 1);
        COMPUTE(ch & 1);
        if (ch + 1 < nk) STORE((ch + 1) & 1);
        __syncthreads();
    }

#pragma unroll
    for (int mt = 0; mt < 4; mt++) {
        int r1 = row0 + wm + mt * 16 + gid;
#pragma unroll
        for (int nt = 0; nt < 4; nt++) {
            int c0 = col0 + wn + nt * 8 + qid * 2;
            float b0 = 0.f, b1 = 0.f;
            if (bias) {
                if (c0 < N) b0 = bias[c0];
                if (c0 + 1 < N) b1 = bias[c0 + 1];
            }
            if (c0 < N) {
                C[(size_t)r1 * ldc + c0] = acc[mt][nt][0] + b0;
                C[(size_t)(r1 + 8) * ldc + c0] = acc[mt][nt][2] + b0;
            }
            if (c0 + 1 < N) {
                C[(size_t)r1 * ldc + c0 + 1] = acc[mt][nt][1] + b1;
                C[(size_t)(r1 + 8) * ldc + c0 + 1] = acc[mt][nt][3] + b1;
            }
        }
    }
}

// ------------- persistent encoder layer: all T steps in one launch ----------
__global__ void __launch_bounds__(256, 2)
enc_persist_kernel(const float* __restrict__ Gx,   // [t*B+b][G8] interleaved
                   const float* __restrict__ Wh,   // [2][G4][H]
                   float* __restrict__ h,          // [2 parity][2 dir][B][H]
                   float* __restrict__ c,
                   float* __restrict__ outseq) {   // [T][B][H2]
    const int dir = blockIdx.y;
    const int j0 = blockIdx.x * 4;
    const int tid = threadIdx.x;
    const int tx = tid & 15, ty = tid >> 4, rb = ty * 4;
    const unsigned nb = gridDim.x * gridDim.y;

    __shared__ float Wsf[16][517];
    __shared__ float As[2][12][68];
    __shared__ float gsm[64][17];

    const float* whd = Wh + (size_t)dir * G4 * H;
    for (int idx = tid; idx < 16 * H; idx += 256) {
        int r = idx / H, k = idx % H;
        int rq = r >> 2, ru = r & 3;
        Wsf[r][k] = whd[(size_t)(rq * H + j0 + ru) * H + k];
    }
    __syncthreads();

    const int SBH_ = B * H, S2_ = 2 * SBH_;
    const int eb0 = tid / 12,         ek0 = tid % 12;
    const int eb1 = (tid + 256) / 12, ek1 = (tid + 256) % 12;
    const int eb2 = (tid + 512) / 12, ek2 = (tid + 512) % 12;

    for (int s = 0; s < T; s++) {
        const int t = dir ? (T - 1 - s) : s;
        const float* hp = h + (s & 1) * S2_ + dir * SBH_;
        float* hn = h + ((s + 1) & 1) * S2_ + dir * SBH_;
        const float* cp_ = c + (s & 1) * S2_ + dir * SBH_;
        float* cn_ = c + ((s + 1) & 1) * S2_ + dir * SBH_;

        As[0][ek0][eb0] = hp[eb0 * H + ek0];
        As[0][ek1][eb1] = hp[eb1 * H + ek1];
        As[0][ek2][eb2] = hp[eb2 * H + ek2];
        __syncthreads();

        unsigned long long acc01 = 0ull, acc23 = 0ull;
        for (int kc = 0; kc < 43; kc++) {     // 516 = 43*12
            const int buf = kc & 1;
            float pf0 = 0.f, pf1 = 0.f, pf2 = 0.f;
            if (kc < 42) {
                int base = (kc + 1) * 12;
                pf0 = hp[eb0 * H + base + ek0];
                pf1 = hp[eb1 * H + base + ek1];
                pf2 = hp[eb2 * H + base + ek2];
            }
#pragma unroll
            for (int kk = 0; kk < 12; kk++) {
                const unsigned long long* h2 =
                    (const unsigned long long*)&As[buf][kk][rb];
                unsigned long long h01 = h2[0], h23 = h2[1];
                float w = Wsf[tx][kc * 12 + kk];
                unsigned long long wp = pack2(w, w);
                fma2(acc01, wp, h01);
                fma2(acc23, wp, h23);
            }
            if (kc < 42) {
                As[buf ^ 1][ek0][eb0] = pf0;
                As[buf ^ 1][ek1][eb1] = pf1;
                As[buf ^ 1][ek2][eb2] = pf2;
            }
            __syncthreads();
        }

        float a0, a1, a2, a3;
        unpack2(acc01, a0, a1);
        unpack2(acc23, a2, a3);
        gsm[rb + 0][tx] = a0; gsm[rb + 1][tx] = a1;
        gsm[rb + 2][tx] = a2; gsm[rb + 3][tx] = a3;
        __syncthreads();

        {
            int bb = tid >> 2, uu = tid & 3;
            int j = j0 + uu;
            const float* gx = Gx + ((size_t)t * B + bb) * G8 + dir * G4 + j;
            float gi = gsm[bb][uu]      + gx[0];
            float gf = gsm[bb][4 + uu]  + gx[H];
            float gg = gsm[bb][8 + uu]  + gx[2 * H];
            float go = gsm[bb][12 + uu] + gx[3 * H];
            float cp = cp_[bb * H + j];
            float si = 1.f / (1.f + expf(-gi));
            float sf = 1.f / (1.f + expf(-gf));
            float so = 1.f / (1.f + expf(-go));
            float cn = fmaf(sf, cp, si * tanhf(gg));
            float hn_ = so * tanhf(cn);
            cn_[bb * H + j] = cn;
            hn[bb * H + j] = hn_;
            outseq[((size_t)t * B + bb) * H2 + dir * H + j] = hn_;
        }
        if (s < T - 1) grid_barrier(nb);
    }
}

// ------------------------- decoder LSTM cell (1 step) -----------------------
__global__ void dec_cell_kernel(const float* __restrict__ x, int Kx,
                                const float* __restrict__ Wi,
                                const float* __restrict__ Wh,
                                const float* __restrict__ bias,
                                const float* __restrict__ hprev, float* __restrict__ hnext,
                                const float* __restrict__ cprev, float* __restrict__ cnext,
                                float* __restrict__ outcat, int outld) {
    const int dir = blockIdx.y;
    const int j0 = blockIdx.x * 4;
    const int tid = threadIdx.x;
    const int tx = tid & 15, ty = tid >> 4, rb = ty * 4;

    __shared__ float As[12][68];
    __shared__ float Ws[16][13];
    __shared__ float gsm[64][17];

    float acc0 = 0.f, acc1 = 0.f, acc2 = 0.f, acc3 = 0.f;

    for (int ph = 0; ph < 2; ph++) {
        const float* A = (ph == 0) ? x : (hprev + dir * (B * H));
        const int K = (ph == 0) ? Kx : H;
        const float* W = (ph == 0) ? (Wi + (size_t)dir * G4 * Kx)
                                   : (Wh + (size_t)dir * G4 * H);
        for (int k0 = 0; k0 < K; k0 += 12) {
            int rem = K - k0; if (rem > 12) rem = 12;
            for (int idx = tid; idx < 64 * 12; idx += 256) {
                int bb = idx / 12, kk = idx % 12;
                As[kk][bb] = (kk < rem) ? A[bb * K + k0 + kk] : 0.f;
            }
            if (tid < 192) {
                int r = tid / 12, kk = tid % 12;
                int rq = r >> 2, ru = r & 3;
                float wv = 0.f;
                if (kk < rem)
                    wv = W[(size_t)(rq * H + j0 + ru) * K + k0 + kk];
                Ws[r][kk] = wv;
            }
            __syncthreads();
#pragma unroll
            for (int kk = 0; kk < 12; kk++) {
                float4 hv = *(const float4*)&As[kk][rb];
                float w = Ws[tx][kk];
                acc0 = fmaf(hv.x, w, acc0);
                acc1 = fmaf(hv.y, w, acc1);
                acc2 = fmaf(hv.z, w, acc2);
                acc3 = fmaf(hv.w, w, acc3);
            }
            __syncthreads();
        }
    }

    gsm[rb + 0][tx] = acc0; gsm[rb + 1][tx] = acc1;
    gsm[rb + 2][tx] = acc2; gsm[rb + 3][tx] = acc3;
    __syncthreads();

    {
        int bb = tid >> 2, uu = tid & 3;
        int j = j0 + uu;
        const float* bz = bias + dir * G4;
        float gi = gsm[bb][uu]      + bz[j];
        float gf = gsm[bb][4 + uu]  + bz[H + j];
        float gg = gsm[bb][8 + uu]  + bz[2 * H + j];
        float go = gsm[bb][12 + uu] + bz[3 * H + j];
        float cp = cprev[dir * B * H + bb * H + j];
        float si = 1.f / (1.f + expf(-gi));
        float sf = 1.f / (1.f + expf(-gf));
        float so = 1.f / (1.f + expf(-go));
        float cn = fmaf(sf, cp, si * tanhf(gg));
        float hn = so * tanhf(cn);
        cnext[dir * B * H + bb * H + j] = cn;
        hnext[dir * B * H + bb * H + j] = hn;
        outcat[bb * outld + dir * H + j] = hn;
    }
}

// -------------------- skinny GEMM: C[64,N] = A@W^T (+b, tanh) ---------------
__global__ void skinny64_nt_kernel(int N, int K,
                                   const float* __restrict__ A, int lda,
                                   const float* __restrict__ W, int ldw,
                                   const float* __restrict__ bias,
                                   float* __restrict__ C, int ldc, int act) {
    __shared__ float As[16][68];
    __shared__ float Ws[16][17];
    const int tid = threadIdx.x;
    const int tx = tid & 15, ty = tid >> 4;
    const int col = blockIdx.x * 16 + tx;

    float acc[4] = {0.f, 0.f, 0.f, 0.f};

    for (int k0 = 0; k0 < K; k0 += 16) {
        for (int idx = tid; idx < 64 * 16; idx += 256) {
            int r = idx >> 4, kk = idx & 15;
            As[kk][r] = (k0 + kk < K) ? A[(size_t)r * lda + k0 + kk] : 0.f;
        }
        {
            int cix = tid & 15, kk = tid >> 4;
            int cg = blockIdx.x * 16 + cix;
            float wv = 0.f;
            if (cg < N && (k0 + kk) < K)
                wv = W[(size_t)cg * ldw + k0 + kk];
            Ws[cix][kk] = wv;
        }
        __syncthreads();
#pragma unroll
        for (int kk = 0; kk < 16; kk++) {
            float w = Ws[tx][kk];
            float4 a = *(const float4*)&As[kk][ty * 4];
            acc[0] = fmaf(a.x, w, acc[0]);
            acc[1] = fmaf(a.y, w, acc[1]);
            acc[2] = fmaf(a.z, w, acc[2]);
            acc[3] = fmaf(a.w, w, acc[3]);
        }
        __syncthreads();
    }

    if (col < N) {
#pragma unroll
        for (int i = 0; i < 4; i++) {
            int r = ty * 4 + i;
            float v = acc[i];
            if (bias) v += bias[col];
            if (act) v = tanhf(v);
            C[(size_t)r * ldc + col] = v;
        }
    }
}

// ------------------------------ attention ----------------------------------
// score[b*T+t] = sum_h v[h]*tanh_approx(E2[(t*B+b)*H2+h] + dbuf[b*H2+h])
__global__ void score_kernel(const float* __restrict__ E2,
                             const float* __restrict__ dbuf,
                             const float* __restrict__ v,
                             float* __restrict__ score) {
    int w = blockIdx.x * 8 + (threadIdx.x >> 5);
    int lane = threadIdx.x & 31;
    int bb = w & 63, t = w >> 6;
    const float4* e = (const float4*)(E2 + (size_t)w * H2);
    const float4* d = (const float4*)(dbuf + (size_t)bb * H2);
    const float4* vv = (const float4*)v;
    float s = 0.f;
    for (int q = lane; q < H2 / 4; q += 32) {   // 258 float4 groups
        float4 ev = e[q], dv = d[q], vq = vv[q];
        s = fmaf(vq.x, ftanh(ev.x + dv.x), s);
        s = fmaf(vq.y, ftanh(ev.y + dv.y), s);
        s = fmaf(vq.z, ftanh(ev.z + dv.z), s);
        s = fmaf(vq.w, ftanh(ev.w + dv.w), s);
    }
#pragma unroll
    for (int o = 16; o > 0; o >>= 1)
        s += __shfl_down_sync(0xffffffffu, s, o);
    if (lane == 0) score[bb * T + t] = s;
}

// fused softmax over T + context accumulation. block = b, 512 threads.
__global__ void attn_kernel(const float* __restrict__ score,
                            const float* __restrict__ enc,
                            float* __restrict__ cc) {
    __shared__ float sm[T];
    __shared__ float aws[T];
    int bb = blockIdx.x, tid = threadIdx.x;
    float v = score[bb * T + tid];
    sm[tid] = v;
    __syncthreads();
    for (int st = 256; st > 0; st >>= 1) {
        if (tid < st) sm[tid] = fmaxf(sm[tid], sm[tid + st]);
        __syncthreads();
    }
    float mx = sm[0];
    __syncthreads();
    float e = expf(v - mx);
    sm[tid] = e;
    __syncthreads();
    for (int st = 256; st > 0; st >>= 1) {
        if (tid < st) sm[tid] += sm[tid + st];
        __syncthreads();
    }
    aws[tid] = e / sm[0];
    __syncthreads();

    float acc[3] = {0.f, 0.f, 0.f};
    for (int t = 0; t < T; t++) {
        float wt = aws[t];
        const float* ep = enc + ((size_t)t * B + bb) * H2;
#pragma unroll
        for (int j = 0; j < 3; j++) {
            int hh = tid + j * 512;
            if (hh < H2) acc[j] = fmaf(wt, ep[hh], acc[j]);
        }
    }
#pragma unroll
    for (int j = 0; j < 3; j++) {
        int hh = tid + j * 512;
        if (hh < H2) cc[bb * (2 * H2) + H2 + hh] = acc[j];
    }
}

// -------------- fused logits + cross-entropy (single block, det.) -----------
__global__ void ce_fused_kernel(const float* __restrict__ co,
                                const float* __restrict__ out_W,
                                const float* __restrict__ out_b,
                                const int* __restrict__ lab,
                                float* __restrict__ loss) {
    __shared__ float lg[64][20];
    __shared__ float red[64];
    int tid = threadIdx.x;           // 1024 threads
    int bb = tid >> 4, slot = tid & 15;
    for (int cix = slot; cix < SEQ; cix += 16) {
        const float* a = co + bb * H2;
        const float* w = out_W + cix * H2;
        float s = out_b[cix];
#pragma unroll 4
        for (int k = 0; k < H2; k++) s = fmaf(a[k], w[k], s);
        lg[bb][cix] = s;
    }
    __syncthreads();
    if (slot == 0) {
        float m = lg[bb][0];
#pragma unroll
        for (int i = 1; i < SEQ; i++) m = fmaxf(m, lg[bb][i]);
        float s = 0.f;
#pragma unroll
        for (int i = 0; i < SEQ; i++) s += expf(lg[bb][i] - m);
        red[bb] = -(lg[bb][lab[bb]] - m - logf(s));
    }
    __syncthreads();
    if (tid == 0) {
        float tot = 0.f;
        for (int i = 0; i < 64; i++) tot += red[i];
        loss[0] += tot / 64.f;
    }
}

// ------------------------------- host --------------------------------------
static float* symaddr(const void* devsym) {
    void* p = nullptr;
    cudaGetSymbolAddress(&p, devsym);
    return (float*)p;
}

extern "C" void kernel_launch(void* const* d_in, const int* in_sizes, int n_in,
                              void* d_out, int out_size) {
    (void)in_sizes; (void)n_in; (void)out_size;
    const float* x        = (const float*)d_in[0];
    const float* y        = (const float*)d_in[1];
    const int*   label    = (const int*)d_in[2];
    const float* expand_W = (const float*)d_in[3];
    const float* expand_b = (const float*)d_in[4];
    const float* eWi0     = (const float*)d_in[5];
    const float* eWh0     = (const float*)d_in[6];
    const float* eb0      = (const float*)d_in[7];
    const float* eWi1     = (const float*)d_in[8];
    const float* eWh1     = (const float*)d_in[9];
    const float* eb1      = (const float*)d_in[10];
    const float* dWi0     = (const float*)d_in[11];
    const float* dWh0     = (const float*)d_in[12];
    const float* db0      = (const float*)d_in[13];
    const float* dWi1     = (const float*)d_in[14];
    const float* dWh1     = (const float*)d_in[15];
    const float* db1      = (const float*)d_in[16];
    const float* attn_W   = (const float*)d_in[17];
    const float* attn_b   = (const float*)d_in[18];
    const float* attn_v   = (const float*)d_in[19];
    const float* concat_W = (const float*)d_in[20];
    const float* concat_b = (const float*)d_in[21];
    const float* out_W    = (const float*)d_in[22];
    const float* out_b    = (const float*)d_in[23];

    float* Gx     = symaddr(&g_Gx);
    float* out0   = symaddr(&g_out0);
    float* outenc = symaddr(&g_outenc);
    float* E2     = symaddr(&g_E2);
    float* Wc     = symaddr(&g_Wc);
    float* bc     = symaddr(&g_bc);
    float* eh     = symaddr(&g_eh);
    float* ec     = symaddr(&g_ec);
    float* dh     = symaddr(&g_dh);
    float* dc     = symaddr(&g_dc);
    float* l0     = symaddr(&g_l0);
    float* cc     = symaddr(&g_cc);
    float* dbuf   = symaddr(&g_dbuf);
    float* co     = symaddr(&g_co);
    float* score  = symaddr(&g_score);
    float* loss   = symaddr(&g_loss);

    const int SBH = B * H;
    const int S2  = 2 * SBH;
    const int S4  = 4 * SBH;

    zero_kernel<<<1, 32>>>(loss, 1);
    zero_kernel<<<(S2 + 255) / 256, 256>>>(eh, S2);
    zero_kernel<<<(S2 + 255) / 256, 256>>>(ec, S2);

    // ---- encoder layer 0: fold expand into Wi, then K=4 "GEMM" ----
    fold0_kernel<<<(G8 + 127) / 128, 128>>>(eWi0, expand_W, expand_b, eb0, Wc, bc);
    gx0_kernel<<<dim3(33, TB / 64), 256>>>(x, Wc, bc, Gx);
    enc_persist_kernel<<<dim3(129, 2), 256>>>(Gx, eWh0, eh, ec, out0);
    copy2_kernel<<<(S2 + 255) / 256, 256>>>(eh, ec, dh, dc, S2);

    // ---- encoder layer 1 ----
    zero_kernel<<<(S2 + 255) / 256, 256>>>(eh, S2);
    zero_kernel<<<(S2 + 255) / 256, 256>>>(ec, S2);
    mma_nt_kernel<<<dim3((G8 + 127) / 128, TB / 128), 256>>>(
        TB, G8, H2, out0, H2, eWi1, H2, eb1, Gx, G8);
    enc_persist_kernel<<<dim3(129, 2), 256>>>(Gx, eWh1, eh, ec, outenc);
    copy2_kernel<<<(S2 + 255) / 256, 256>>>(eh, ec, dh + S2, dc + S2, S2);

    // ---- attention precompute: E2 = outenc @ attn_W[:,1032:]^T + attn_b ----
    mma_nt_kernel<<<dim3((H2 + 127) / 128, TB / 128), 256>>>(
        TB, H2, H2, outenc, H2, attn_W + H2, G4, attn_b, E2, H2);

    // ---- decoder loop ----
    for (int ts = 0; ts < NY; ts++) {
        int pp = (ts & 1) * S4, np = ((ts + 1) & 1) * S4;
        dec_cell_kernel<<<dim3(129, 2), 256>>>(
            y + (size_t)ts * B * SEQ, SEQ, dWi0, dWh0, db0,
            dh + pp, dh + np, dc + pp, dc + np, l0, H2);
        dec_cell_kernel<<<dim3(129, 2), 256>>>(
            l0, H2, dWi1, dWh1, db1,
            dh + pp + S2, dh + np + S2, dc + pp + S2, dc + np + S2,
            cc, 2 * H2);
        skinny64_nt_kernel<<<(H2 + 15) / 16, 256>>>(
            H2, H2, cc, 2 * H2, attn_W, G4, nullptr, dbuf, H2, 0);
        score_kernel<<<TB / 8, 256>>>(E2, dbuf, attn_v, score);
        attn_kernel<<<B, 512>>>(score, outenc, cc);
        skinny64_nt_kernel<<<(H2 + 15) / 16, 256>>>(
            H2, G4, cc, 2 * H2, concat_W, G4, concat_b, co, H2, 1);
        ce_fused_kernel<<<1, 1024>>>(co, out_W, out_b, label + ts * B, loss);
    }

    write_out_kernel<<<1, 1>>>((float*)d_out, loss);
}